// round 1
// baseline (speedup 1.0000x reference)
#include <cuda_runtime.h>
#include <math.h>

#define B_ROWS 16384
#define HID    1024
#define NJOUT  256   // 64 joints * 4 quat components
#define NJ     64

// Scratch (allocation-free rule: __device__ globals)
__device__ float g_h1[B_ROWS * HID];
__device__ float g_h2[B_ROWS * HID];
__device__ float g_joints[B_ROWS * NJOUT];

// ---------------------------------------------------------------------------
// Layer 1: [B,3] @ [3,1024] + b1, leaky_relu. Memory bound.
// ---------------------------------------------------------------------------
__global__ void layer1_kernel(const float* __restrict__ x,
                              const float* __restrict__ W1,
                              const float* __restrict__ b1,
                              float* __restrict__ out)
{
    int idx = blockIdx.x * blockDim.x + threadIdx.x;   // over B*1024
    int i = idx >> 10;
    int j = idx & 1023;
    float x0 = x[i * 3 + 0];
    float x1 = x[i * 3 + 1];
    float x2 = x[i * 3 + 2];
    float v = b1[j];
    v = fmaf(x0, W1[j],        v);
    v = fmaf(x1, W1[1024 + j], v);
    v = fmaf(x2, W1[2048 + j], v);
    out[idx] = (v >= 0.0f) ? v : 0.01f * v;
}

// ---------------------------------------------------------------------------
// Tiled SGEMM: C[B,N] = act(A[B,1024] @ W[1024,N] + bias)
// BM=128, BN=128, BK=16, 256 threads, 8x8 per-thread tile, smem double buffer.
// ACT: 0 = leaky_relu, 1 = tanh
// ---------------------------------------------------------------------------
template<int ACT>
__global__ void __launch_bounds__(256, 2)
gemm_kernel(const float* __restrict__ A,
            const float* __restrict__ W,
            const float* __restrict__ bias,
            float* __restrict__ C, int N)
{
    __shared__ float As[2][16][128];   // transposed A tile: As[k][row]
    __shared__ float Bs[2][16][128];   // Bs[k][col]

    const int K = 1024;
    const int tid = threadIdx.x;
    const int rowBase = blockIdx.y * 128;
    const int colBase = blockIdx.x * 128;

    // Per-thread load slots: 2x float4 from A, 2x float4 from W per tile.
    const int f0 = tid, f1 = tid + 256;
    const int aRow0 = f0 >> 2, aK0 = (f0 & 3) * 4;
    const int aRow1 = f1 >> 2, aK1 = (f1 & 3) * 4;
    const int bRow0 = f0 >> 5, bCol0 = (f0 & 31) * 4;
    const int bRow1 = f1 >> 5, bCol1 = (f1 & 31) * 4;

    const float* Ap0 = A + (size_t)(rowBase + aRow0) * K + aK0;
    const float* Ap1 = A + (size_t)(rowBase + aRow1) * K + aK1;
    const float* Bp0 = W + (size_t)bRow0 * N + colBase + bCol0;
    const float* Bp1 = W + (size_t)bRow1 * N + colBase + bCol1;

    // Tile 0 -> smem buffer 0
    {
        float4 a0 = *(const float4*)Ap0;
        float4 a1 = *(const float4*)Ap1;
        float4 b0 = *(const float4*)Bp0;
        float4 b1 = *(const float4*)Bp1;
        As[0][aK0 + 0][aRow0] = a0.x; As[0][aK0 + 1][aRow0] = a0.y;
        As[0][aK0 + 2][aRow0] = a0.z; As[0][aK0 + 3][aRow0] = a0.w;
        As[0][aK1 + 0][aRow1] = a1.x; As[0][aK1 + 1][aRow1] = a1.y;
        As[0][aK1 + 2][aRow1] = a1.z; As[0][aK1 + 3][aRow1] = a1.w;
        *(float4*)&Bs[0][bRow0][bCol0] = b0;
        *(float4*)&Bs[0][bRow1][bCol1] = b1;
    }
    __syncthreads();

    const int ty = tid >> 4;   // 0..15 -> row group (8 rows)
    const int tx = tid & 15;   // 0..15 -> col group (8 cols)

    float acc[8][8];
    #pragma unroll
    for (int i = 0; i < 8; i++)
        #pragma unroll
        for (int j = 0; j < 8; j++) acc[i][j] = 0.0f;

    const int NT = K / 16;   // 64 tiles
    for (int t = 0; t < NT; t++) {
        const int buf = t & 1;
        float4 pa0, pa1, pb0, pb1;
        if (t + 1 < NT) {
            pa0 = *(const float4*)(Ap0 + (t + 1) * 16);
            pa1 = *(const float4*)(Ap1 + (t + 1) * 16);
            pb0 = *(const float4*)(Bp0 + (size_t)(t + 1) * 16 * N);
            pb1 = *(const float4*)(Bp1 + (size_t)(t + 1) * 16 * N);
        }
        #pragma unroll
        for (int k = 0; k < 16; k++) {
            float4 a0 = *(const float4*)&As[buf][k][ty * 8];
            float4 a1 = *(const float4*)&As[buf][k][ty * 8 + 4];
            float4 b0 = *(const float4*)&Bs[buf][k][tx * 8];
            float4 b1 = *(const float4*)&Bs[buf][k][tx * 8 + 4];
            float ra[8] = {a0.x, a0.y, a0.z, a0.w, a1.x, a1.y, a1.z, a1.w};
            float rb[8] = {b0.x, b0.y, b0.z, b0.w, b1.x, b1.y, b1.z, b1.w};
            #pragma unroll
            for (int i = 0; i < 8; i++)
                #pragma unroll
                for (int j = 0; j < 8; j++)
                    acc[i][j] = fmaf(ra[i], rb[j], acc[i][j]);
        }
        if (t + 1 < NT) {
            const int nb = buf ^ 1;
            As[nb][aK0 + 0][aRow0] = pa0.x; As[nb][aK0 + 1][aRow0] = pa0.y;
            As[nb][aK0 + 2][aRow0] = pa0.z; As[nb][aK0 + 3][aRow0] = pa0.w;
            As[nb][aK1 + 0][aRow1] = pa1.x; As[nb][aK1 + 1][aRow1] = pa1.y;
            As[nb][aK1 + 2][aRow1] = pa1.z; As[nb][aK1 + 3][aRow1] = pa1.w;
            *(float4*)&Bs[nb][bRow0][bCol0] = pb0;
            *(float4*)&Bs[nb][bRow1][bCol1] = pb1;
            __syncthreads();
        }
    }

    // Epilogue: bias + activation, vectorized stores.
    float4 bv0 = *(const float4*)&bias[colBase + tx * 8];
    float4 bv1 = *(const float4*)&bias[colBase + tx * 8 + 4];
    float bb[8] = {bv0.x, bv0.y, bv0.z, bv0.w, bv1.x, bv1.y, bv1.z, bv1.w};

    #pragma unroll
    for (int i = 0; i < 8; i++) {
        int r = rowBase + ty * 8 + i;
        float* Crow = C + (size_t)r * N + colBase + tx * 8;
        float v[8];
        #pragma unroll
        for (int j = 0; j < 8; j++) {
            float s = acc[i][j] + bb[j];
            if (ACT == 0) v[j] = (s >= 0.0f) ? s : 0.01f * s;
            else          v[j] = tanhf(s);
        }
        float4 o0 = make_float4(v[0], v[1], v[2], v[3]);
        float4 o1 = make_float4(v[4], v[5], v[6], v[7]);
        *(float4*)&Crow[0] = o0;
        *(float4*)&Crow[4] = o1;
    }
}

// ---------------------------------------------------------------------------
// FK chain: one thread per row. Homogeneous bottom row stays (0,0,0,1)
// exactly, and fp32(1 + 1e-9) == 1, so the division is identity.
// coordi = R @ T  =>  3x3 = R3, translation = R3 column 1.
// cur = prev @ coordi => M = M@R3, p = M_prev@R3[:,1] + p.
// ---------------------------------------------------------------------------
__global__ void fk_kernel(const float* __restrict__ joints,
                          float* __restrict__ out)
{
    int row = blockIdx.x * blockDim.x + threadIdx.x;
    if (row >= B_ROWS) return;

    const float* q = joints + (size_t)row * NJOUT;
    float* o = out + (size_t)row * (NJ * 3);

    float M00 = 1, M01 = 0, M02 = 0;
    float M10 = 0, M11 = 1, M12 = 0;
    float M20 = 0, M21 = 0, M22 = 1;
    float px = 0, py = 0, pz = 0;

    for (int j = 0; j < NJ; j++) {
        float4 qv = *(const float4*)(q + 4 * j);
        float w = qv.x, x = qv.y, y = qv.z, z = qv.w;
        float s = 2.0f / (w * w + x * x + y * y + z * z);

        float r00 = 1.0f - s * (y * y + z * z);
        float r01 = s * (x * y - z * w);
        float r02 = s * (x * z + y * w);
        float r10 = s * (x * y + z * w);
        float r11 = 1.0f - s * (x * x + z * z);
        float r12 = s * (y * z - x * w);
        float r20 = s * (x * z - y * w);
        float r21 = s * (y * z + x * w);
        float r22 = 1.0f - s * (x * x + y * y);

        // translation = M @ R[:,1] + p
        float tx = M00 * r01 + M01 * r11 + M02 * r21 + px;
        float ty = M10 * r01 + M11 * r11 + M12 * r21 + py;
        float tz = M20 * r01 + M21 * r11 + M22 * r21 + pz;

        // M = M @ R
        float n00 = M00 * r00 + M01 * r10 + M02 * r20;
        float n01 = M00 * r01 + M01 * r11 + M02 * r21;
        float n02 = M00 * r02 + M01 * r12 + M02 * r22;
        float n10 = M10 * r00 + M11 * r10 + M12 * r20;
        float n11 = M10 * r01 + M11 * r11 + M12 * r21;
        float n12 = M10 * r02 + M11 * r12 + M12 * r22;
        float n20 = M20 * r00 + M21 * r10 + M22 * r20;
        float n21 = M20 * r01 + M21 * r11 + M22 * r21;
        float n22 = M20 * r02 + M21 * r12 + M22 * r22;

        M00 = n00; M01 = n01; M02 = n02;
        M10 = n10; M11 = n11; M12 = n12;
        M20 = n20; M21 = n21; M22 = n22;
        px = tx; py = ty; pz = tz;

        o[3 * j + 0] = px;
        o[3 * j + 1] = py;
        o[3 * j + 2] = pz;
    }
}

// ---------------------------------------------------------------------------
extern "C" void kernel_launch(void* const* d_in, const int* in_sizes, int n_in,
                              void* d_out, int out_size)
{
    const float* x  = (const float*)d_in[0];
    const float* W1 = (const float*)d_in[1];
    const float* b1 = (const float*)d_in[2];
    const float* W2 = (const float*)d_in[3];
    const float* b2 = (const float*)d_in[4];
    const float* W3 = (const float*)d_in[5];
    const float* b3 = (const float*)d_in[6];
    const float* W4 = (const float*)d_in[7];
    const float* b4 = (const float*)d_in[8];
    float* out = (float*)d_out;

    // Symbol addresses (pure host-side query; capture-legal, no allocation)
    void *p_h1 = nullptr, *p_h2 = nullptr, *p_jt = nullptr;
    cudaGetSymbolAddress(&p_h1, g_h1);
    cudaGetSymbolAddress(&p_h2, g_h2);
    cudaGetSymbolAddress(&p_jt, g_joints);
    float* h1 = (float*)p_h1;
    float* h2 = (float*)p_h2;
    float* jt = (float*)p_jt;

    // Layer 1: x @ W1 -> h1
    layer1_kernel<<<(B_ROWS * HID) / 256, 256>>>(x, W1, b1, h1);

    // Layer 2: h1 @ W2 -> h2
    {
        dim3 grid(HID / 128, B_ROWS / 128);
        gemm_kernel<0><<<grid, 256>>>(h1, W2, b2, h2, HID);
    }
    // Layer 3: h2 @ W3 -> h1 (reuse)
    {
        dim3 grid(HID / 128, B_ROWS / 128);
        gemm_kernel<0><<<grid, 256>>>(h2, W3, b3, h1, HID);
    }
    // Layer 4: h1 @ W4 -> joints (tanh)
    {
        dim3 grid(NJOUT / 128, B_ROWS / 128);
        gemm_kernel<1><<<grid, 256>>>(h1, W4, b4, jt, NJOUT);
    }
    // FK chain -> out
    fk_kernel<<<B_ROWS / 128, 128>>>(jt, out);
}

// round 6
// speedup vs baseline: 2.9488x; 2.9488x over previous
#include <cuda_runtime.h>
#include <cuda_bf16.h>
#include <cstdint>
#include <math.h>

#define B_ROWS 16384
#define HID    1024
#define NJOUT  256
#define NJ     64

// ---------------------------------------------------------------------------
// Scratch (__device__ globals; allocation-free rule)
// Activations: [B, 2048] bf16 -> cols 0..1023 = hi plane, 1024..2047 = lo plane
// Weights:     [N, 2048] bf16 (transposed, K-major), hi|lo planes
// ---------------------------------------------------------------------------
__device__ __nv_bfloat16 g_act0[B_ROWS * 2048];
__device__ __nv_bfloat16 g_act1[B_ROWS * 2048];
__device__ __nv_bfloat16 g_w2t[HID * 2048];
__device__ __nv_bfloat16 g_w3t[HID * 2048];
__device__ __nv_bfloat16 g_w4t[NJOUT * 2048];
__device__ float         g_joints[B_ROWS * NJOUT];

__device__ __forceinline__ uint32_t smem_u32(const void* p) {
    uint32_t a;
    asm("{ .reg .u64 t; cvta.to.shared.u64 t, %1; cvt.u32.u64 %0, t; }"
        : "=r"(a) : "l"(p));
    return a;
}

// ---------------------------------------------------------------------------
// Weight split+transpose: W[K,N] fp32 -> out[N, 2K] bf16 (hi plane | lo plane)
// ---------------------------------------------------------------------------
__global__ void wsplit_kernel(const float* __restrict__ W,
                              __nv_bfloat16* __restrict__ out, int K, int N)
{
    int idx = blockIdx.x * blockDim.x + threadIdx.x;
    if (idx >= N * K) return;
    int n = idx / K;
    int k = idx - n * K;
    float v = W[(size_t)k * N + n];
    __nv_bfloat16 hi = __float2bfloat16(v);
    __nv_bfloat16 lo = __float2bfloat16(v - __bfloat162float(hi));
    out[(size_t)n * 2048 + k] = hi;
    out[(size_t)n * 2048 + 1024 + k] = lo;
}

// ---------------------------------------------------------------------------
// Layer 1: [B,3]@[3,1024]+b1, leaky -> split bf16 to g_act0 [B,2048]
// ---------------------------------------------------------------------------
__global__ void layer1_kernel(const float* __restrict__ x,
                              const float* __restrict__ W1,
                              const float* __restrict__ b1,
                              __nv_bfloat16* __restrict__ out)
{
    int idx = blockIdx.x * blockDim.x + threadIdx.x;
    int i = idx >> 10;
    int j = idx & 1023;
    float x0 = x[i * 3 + 0], x1 = x[i * 3 + 1], x2 = x[i * 3 + 2];
    float v = b1[j];
    v = fmaf(x0, W1[j],        v);
    v = fmaf(x1, W1[1024 + j], v);
    v = fmaf(x2, W1[2048 + j], v);
    v = (v >= 0.0f) ? v : 0.01f * v;
    __nv_bfloat16 hi = __float2bfloat16(v);
    __nv_bfloat16 lo = __float2bfloat16(v - __bfloat162float(hi));
    out[(size_t)i * 2048 + j] = hi;
    out[(size_t)i * 2048 + 1024 + j] = lo;
}

// ---------------------------------------------------------------------------
// HMMA GEMM: C[B,N] = act(A @ W^T + bias), split-bf16 3-pass accumulate.
//   A2: [B,2048] bf16 (hi|lo),  BT: [N,2048] bf16 (hi|lo, K-major)
//   CTA tile 128x128, 8 warps (2x4), warp tile 64x32, mma m16n8k16.
//   BK=64 (128B rows, XOR swizzle), cp.async double buffer, 48 chunks.
// ---------------------------------------------------------------------------
#define NCHUNK 48
#define SMEM_REQ 69632

template<int ACT, int OUT_SPLIT>
__global__ void __launch_bounds__(256, 2)
mma_gemm(const __nv_bfloat16* __restrict__ A2,
         const __nv_bfloat16* __restrict__ BT,
         const float* __restrict__ bias,
         void* __restrict__ outp)
{
    extern __shared__ char dsmem[];
    const uint32_t sraw = smem_u32(dsmem);
    const uint32_t S = (sraw + 127u) & ~127u;
    char* Sp = dsmem + (S - sraw);

    const int tid = threadIdx.x;
    const int lane = tid & 31;
    const int wid = tid >> 5;
    const int warp_m = wid & 1;     // 2 warp-rows of 64
    const int warp_n = wid >> 1;    // 4 warp-cols of 32
    const int rowBase = blockIdx.y * 128;
    const int colBase = blockIdx.x * 128;

    const uint32_t Abuf = S;            // 2 x 16KB
    const uint32_t Bbuf = S + 32768;    // 2 x 16KB

    const int ldRow = tid >> 3;   // 0..31 (+32/iter)
    const int ldCh  = tid & 7;    // 16B chunk within 128B row

    float acc[4][4][4];
    #pragma unroll
    for (int i = 0; i < 4; i++)
        #pragma unroll
        for (int j = 0; j < 4; j++)
            #pragma unroll
            for (int r = 0; r < 4; r++) acc[i][j][r] = 0.0f;

    auto load_chunk = [&](int c, int buf) {
        const int pass = c >> 4, kc = c & 15;
        const int aCol = ((pass == 1) ? 1024 : 0) + kc * 64;
        const int bCol = ((pass == 2) ? 1024 : 0) + kc * 64;
        const uint32_t aT = Abuf + buf * 16384;
        const uint32_t bT = Bbuf + buf * 16384;
        #pragma unroll
        for (int it = 0; it < 4; it++) {
            int row = ldRow + it * 32;
            const void* src = A2 + (size_t)(rowBase + row) * 2048 + aCol + ldCh * 8;
            uint32_t dst = aT + row * 128 + ((ldCh ^ (row & 7)) * 16);
            asm volatile("cp.async.cg.shared.global [%0], [%1], 16;\n"
                         :: "r"(dst), "l"(src));
        }
        #pragma unroll
        for (int it = 0; it < 4; it++) {
            int row = ldRow + it * 32;
            const void* src = BT + (size_t)(colBase + row) * 2048 + bCol + ldCh * 8;
            uint32_t dst = bT + row * 128 + ((ldCh ^ (row & 7)) * 16);
            asm volatile("cp.async.cg.shared.global [%0], [%1], 16;\n"
                         :: "r"(dst), "l"(src));
        }
        asm volatile("cp.async.commit_group;\n");
    };

    load_chunk(0, 0);

    // ldmatrix lane mapping
    const int aR = lane & 15;        // row within 16-row m-tile
    const int aH = lane >> 4;        // k half (16B chunk +0/+1)
    const int bR = lane & 7;
    const int bQ = lane >> 3;        // quad 0..3

    for (int c = 0; c < NCHUNK; c++) {
        const int buf = c & 1;
        if (c + 1 < NCHUNK) {
            load_chunk(c + 1, buf ^ 1);
            asm volatile("cp.async.wait_group 1;\n" ::: "memory");
        } else {
            asm volatile("cp.async.wait_group 0;\n" ::: "memory");
        }
        __syncthreads();

        const uint32_t aT = Abuf + buf * 16384;
        const uint32_t bT = Bbuf + buf * 16384;

        #pragma unroll
        for (int ks = 0; ks < 4; ks++) {
            uint32_t bfr[4][2];
            #pragma unroll
            for (int p = 0; p < 2; p++) {
                int nrow = warp_n * 32 + p * 16 + (bQ >> 1) * 8 + bR;
                int ch = ks * 2 + (bQ & 1);
                uint32_t addr = bT + nrow * 128 + ((ch ^ (nrow & 7)) * 16);
                uint32_t x0, x1, x2, x3;
                asm volatile("ldmatrix.sync.aligned.m8n8.x4.shared.b16 "
                             "{%0,%1,%2,%3}, [%4];"
                             : "=r"(x0), "=r"(x1), "=r"(x2), "=r"(x3) : "r"(addr));
                bfr[p * 2 + 0][0] = x0; bfr[p * 2 + 0][1] = x1;
                bfr[p * 2 + 1][0] = x2; bfr[p * 2 + 1][1] = x3;
            }
            #pragma unroll
            for (int i = 0; i < 4; i++) {
                int arow = warp_m * 64 + i * 16 + aR;
                int ch = ks * 2 + aH;
                uint32_t addr = aT + arow * 128 + ((ch ^ (arow & 7)) * 16);
                uint32_t a0, a1, a2, a3;
                asm volatile("ldmatrix.sync.aligned.m8n8.x4.shared.b16 "
                             "{%0,%1,%2,%3}, [%4];"
                             : "=r"(a0), "=r"(a1), "=r"(a2), "=r"(a3) : "r"(addr));
                #pragma unroll
                for (int j = 0; j < 4; j++) {
                    asm volatile(
                        "mma.sync.aligned.m16n8k16.row.col.f32.bf16.bf16.f32 "
                        "{%0,%1,%2,%3}, {%4,%5,%6,%7}, {%8,%9}, {%0,%1,%2,%3};"
                        : "+f"(acc[i][j][0]), "+f"(acc[i][j][1]),
                          "+f"(acc[i][j][2]), "+f"(acc[i][j][3])
                        : "r"(a0), "r"(a1), "r"(a2), "r"(a3),
                          "r"(bfr[j][0]), "r"(bfr[j][1]));
                }
            }
        }
        __syncthreads();
    }

    // ---------------- epilogue: stage fp32 -> smem, then coalesced out ------
    float* stg = (float*)Sp;          // [128][132]
    const int g = lane >> 2, t = lane & 3;
    #pragma unroll
    for (int i = 0; i < 4; i++) {
        int r0 = warp_m * 64 + i * 16 + g;
        #pragma unroll
        for (int j = 0; j < 4; j++) {
            int cc = warp_n * 32 + j * 8 + t * 2;
            *(float2*)&stg[r0 * 132 + cc]       = make_float2(acc[i][j][0], acc[i][j][1]);
            *(float2*)&stg[(r0 + 8) * 132 + cc] = make_float2(acc[i][j][2], acc[i][j][3]);
        }
    }
    __syncthreads();

    if (OUT_SPLIT) {
        __nv_bfloat16* O = (__nv_bfloat16*)outp;
        for (int idx = tid; idx < 128 * 64; idx += 256) {
            int row = idx >> 6, cc = (idx & 63) * 2;
            float v0 = stg[row * 132 + cc]     + bias[colBase + cc];
            float v1 = stg[row * 132 + cc + 1] + bias[colBase + cc + 1];
            if (ACT == 0) {
                v0 = (v0 >= 0.0f) ? v0 : 0.01f * v0;
                v1 = (v1 >= 0.0f) ? v1 : 0.01f * v1;
            } else {
                v0 = tanhf(v0); v1 = tanhf(v1);
            }
            __nv_bfloat16 h0 = __float2bfloat16(v0);
            __nv_bfloat16 l0 = __float2bfloat16(v0 - __bfloat162float(h0));
            __nv_bfloat16 h1 = __float2bfloat16(v1);
            __nv_bfloat16 l1 = __float2bfloat16(v1 - __bfloat162float(h1));
            size_t base = (size_t)(rowBase + row) * 2048 + colBase + cc;
            __nv_bfloat162 hv; hv.x = h0; hv.y = h1;
            __nv_bfloat162 lv; lv.x = l0; lv.y = l1;
            *(__nv_bfloat162*)(O + base)        = hv;
            *(__nv_bfloat162*)(O + base + 1024) = lv;
        }
    } else {
        float* O = (float*)outp;
        for (int idx = tid; idx < 128 * 128; idx += 256) {
            int row = idx >> 7, cc = idx & 127;
            float v = stg[row * 132 + cc] + bias[colBase + cc];
            if (ACT == 0) v = (v >= 0.0f) ? v : 0.01f * v;
            else          v = tanhf(v);
            O[(size_t)(rowBase + row) * 256 + colBase + cc] = v;
        }
    }
}

// ---------------------------------------------------------------------------
// FK chain: one thread per row. Bottom homogeneous row stays (0,0,0,1),
// fp32(1 + 1e-9) == 1, so the final divide is identity.
// ---------------------------------------------------------------------------
__global__ void fk_kernel(const float* __restrict__ joints,
                          float* __restrict__ out)
{
    int row = blockIdx.x * blockDim.x + threadIdx.x;
    if (row >= B_ROWS) return;

    const float* q = joints + (size_t)row * NJOUT;
    float* o = out + (size_t)row * (NJ * 3);

    float M00 = 1, M01 = 0, M02 = 0;
    float M10 = 0, M11 = 1, M12 = 0;
    float M20 = 0, M21 = 0, M22 = 1;
    float px = 0, py = 0, pz = 0;

    for (int j = 0; j < NJ; j++) {
        float4 qv = *(const float4*)(q + 4 * j);
        float w = qv.x, x = qv.y, y = qv.z, z = qv.w;
        float s = 2.0f / (w * w + x * x + y * y + z * z);

        float r00 = 1.0f - s * (y * y + z * z);
        float r01 = s * (x * y - z * w);
        float r02 = s * (x * z + y * w);
        float r10 = s * (x * y + z * w);
        float r11 = 1.0f - s * (x * x + z * z);
        float r12 = s * (y * z - x * w);
        float r20 = s * (x * z - y * w);
        float r21 = s * (y * z + x * w);
        float r22 = 1.0f - s * (x * x + y * y);

        float tx = M00 * r01 + M01 * r11 + M02 * r21 + px;
        float ty = M10 * r01 + M11 * r11 + M12 * r21 + py;
        float tz = M20 * r01 + M21 * r11 + M22 * r21 + pz;

        float n00 = M00 * r00 + M01 * r10 + M02 * r20;
        float n01 = M00 * r01 + M01 * r11 + M02 * r21;
        float n02 = M00 * r02 + M01 * r12 + M02 * r22;
        float n10 = M10 * r00 + M11 * r10 + M12 * r20;
        float n11 = M10 * r01 + M11 * r11 + M12 * r21;
        float n12 = M10 * r02 + M11 * r12 + M12 * r22;
        float n20 = M20 * r00 + M21 * r10 + M22 * r20;
        float n21 = M20 * r01 + M21 * r11 + M22 * r21;
        float n22 = M20 * r02 + M21 * r12 + M22 * r22;

        M00 = n00; M01 = n01; M02 = n02;
        M10 = n10; M11 = n11; M12 = n12;
        M20 = n20; M21 = n21; M22 = n22;
        px = tx; py = ty; pz = tz;

        o[3 * j + 0] = px;
        o[3 * j + 1] = py;
        o[3 * j + 2] = pz;
    }
}

// ---------------------------------------------------------------------------
extern "C" void kernel_launch(void* const* d_in, const int* in_sizes, int n_in,
                              void* d_out, int out_size)
{
    const float* x  = (const float*)d_in[0];
    const float* W1 = (const float*)d_in[1];
    const float* b1 = (const float*)d_in[2];
    const float* W2 = (const float*)d_in[3];
    const float* b2 = (const float*)d_in[4];
    const float* W3 = (const float*)d_in[5];
    const float* b3 = (const float*)d_in[6];
    const float* W4 = (const float*)d_in[7];
    const float* b4 = (const float*)d_in[8];
    float* out = (float*)d_out;

    void *p_a0, *p_a1, *p_w2, *p_w3, *p_w4, *p_jt;
    cudaGetSymbolAddress(&p_a0, g_act0);
    cudaGetSymbolAddress(&p_a1, g_act1);
    cudaGetSymbolAddress(&p_w2, g_w2t);
    cudaGetSymbolAddress(&p_w3, g_w3t);
    cudaGetSymbolAddress(&p_w4, g_w4t);
    cudaGetSymbolAddress(&p_jt, g_joints);
    __nv_bfloat16* a0  = (__nv_bfloat16*)p_a0;
    __nv_bfloat16* a1  = (__nv_bfloat16*)p_a1;
    __nv_bfloat16* w2t = (__nv_bfloat16*)p_w2;
    __nv_bfloat16* w3t = (__nv_bfloat16*)p_w3;
    __nv_bfloat16* w4t = (__nv_bfloat16*)p_w4;
    float* jt = (float*)p_jt;

    cudaFuncSetAttribute(mma_gemm<0, 1>, cudaFuncAttributeMaxDynamicSharedMemorySize, SMEM_REQ);
    cudaFuncSetAttribute(mma_gemm<1, 0>, cudaFuncAttributeMaxDynamicSharedMemorySize, SMEM_REQ);

    // Weight split+transpose
    wsplit_kernel<<<(HID * HID) / 256, 256>>>(W2, w2t, HID, HID);
    wsplit_kernel<<<(HID * HID) / 256, 256>>>(W3, w3t, HID, HID);
    wsplit_kernel<<<(HID * NJOUT) / 256, 256>>>(W4, w4t, HID, NJOUT);

    // Layer 1 (fp32, K=3) -> split act
    layer1_kernel<<<(B_ROWS * HID) / 256, 256>>>(x, W1, b1, a0);

    // Layers 2-4 on HMMA tensor cores
    {
        dim3 grid(HID / 128, B_ROWS / 128);
        mma_gemm<0, 1><<<grid, 256, SMEM_REQ>>>(a0, w2t, b2, a1);
        mma_gemm<0, 1><<<grid, 256, SMEM_REQ>>>(a1, w3t, b3, a0);
    }
    {
        dim3 grid(NJOUT / 128, B_ROWS / 128);
        mma_gemm<1, 0><<<grid, 256, SMEM_REQ>>>(a0, w4t, b4, jt);
    }

    // FK chain
    fk_kernel<<<B_ROWS / 128, 128>>>(jt, out);
}

// round 7
// speedup vs baseline: 3.0577x; 1.0369x over previous
#include <cuda_runtime.h>
#include <cuda_bf16.h>
#include <cstdint>
#include <math.h>

#define B_ROWS 16384
#define HID    1024
#define NJOUT  256
#define NJ     64

// ---------------------------------------------------------------------------
// Scratch (__device__ globals; allocation-free rule)
// Activations: [B, 2048] bf16 -> cols 0..1023 = hi plane, 1024..2047 = lo plane
// Weights:     [N, 2048] bf16 (transposed, K-major), hi|lo planes
// ---------------------------------------------------------------------------
__device__ __nv_bfloat16 g_act0[B_ROWS * 2048];
__device__ __nv_bfloat16 g_act1[B_ROWS * 2048];
__device__ __nv_bfloat16 g_w2t[HID * 2048];
__device__ __nv_bfloat16 g_w3t[HID * 2048];
__device__ __nv_bfloat16 g_w4t[NJOUT * 2048];
__device__ float         g_joints[B_ROWS * NJOUT];

__device__ __forceinline__ uint32_t smem_u32(const void* p) {
    uint32_t a;
    asm("{ .reg .u64 t; cvta.to.shared.u64 t, %1; cvt.u32.u64 %0, t; }"
        : "=r"(a) : "l"(p));
    return a;
}

__device__ __forceinline__ uint32_t pack_bf2(float a, float b) {
    __nv_bfloat162 p;
    p.x = __float2bfloat16(a);
    p.y = __float2bfloat16(b);
    return *(uint32_t*)&p;
}

// ---------------------------------------------------------------------------
// Weight split+transpose (tiled, coalesced both ways):
// W[K,N] fp32 -> out[N, 2K] bf16 (hi plane | lo plane)
// ---------------------------------------------------------------------------
__global__ void wsplit_kernel(const float* __restrict__ W,
                              __nv_bfloat16* __restrict__ out, int K, int N)
{
    __shared__ float s[32][33];
    const int n0 = blockIdx.x * 32;
    const int k0 = blockIdx.y * 32;
    const int tx = threadIdx.x;        // 0..31
    const int ty = threadIdx.y;        // 0..7

    #pragma unroll
    for (int r = ty; r < 32; r += 8)
        s[r][tx] = W[(size_t)(k0 + r) * N + n0 + tx];
    __syncthreads();

    #pragma unroll
    for (int r = ty; r < 32; r += 8) {
        float v = s[tx][r];            // = W[k0+tx][n0+r]
        __nv_bfloat16 hi = __float2bfloat16(v);
        __nv_bfloat16 lo = __float2bfloat16(v - __bfloat162float(hi));
        size_t base = (size_t)(n0 + r) * 2048 + k0 + tx;
        out[base] = hi;
        out[base + 1024] = lo;
    }
}

// ---------------------------------------------------------------------------
// Layer 1: [B,3]@[3,1024]+b1, leaky -> split bf16 [B,2048]. 8 outputs/thread.
// ---------------------------------------------------------------------------
__global__ void layer1_kernel(const float* __restrict__ x,
                              const float* __restrict__ W1,
                              const float* __restrict__ b1,
                              __nv_bfloat16* __restrict__ out)
{
    int t = blockIdx.x * blockDim.x + threadIdx.x;    // B_ROWS*128
    int i = t >> 7;
    int j0 = (t & 127) << 3;

    float x0 = x[i * 3 + 0], x1 = x[i * 3 + 1], x2 = x[i * 3 + 2];

    float v[8];
    {
        float4 ba = *(const float4*)&b1[j0];
        float4 bb = *(const float4*)&b1[j0 + 4];
        v[0] = ba.x; v[1] = ba.y; v[2] = ba.z; v[3] = ba.w;
        v[4] = bb.x; v[5] = bb.y; v[6] = bb.z; v[7] = bb.w;
    }
    #pragma unroll
    for (int r = 0; r < 3; r++) {
        float xr = (r == 0) ? x0 : (r == 1) ? x1 : x2;
        float4 wa = *(const float4*)&W1[r * 1024 + j0];
        float4 wb = *(const float4*)&W1[r * 1024 + j0 + 4];
        v[0] = fmaf(xr, wa.x, v[0]); v[1] = fmaf(xr, wa.y, v[1]);
        v[2] = fmaf(xr, wa.z, v[2]); v[3] = fmaf(xr, wa.w, v[3]);
        v[4] = fmaf(xr, wb.x, v[4]); v[5] = fmaf(xr, wb.y, v[5]);
        v[6] = fmaf(xr, wb.z, v[6]); v[7] = fmaf(xr, wb.w, v[7]);
    }

    uint4 hp, lp;
    uint32_t* hw = (uint32_t*)&hp;
    uint32_t* lw = (uint32_t*)&lp;
    #pragma unroll
    for (int p = 0; p < 4; p++) {
        float a = v[2 * p], b = v[2 * p + 1];
        a = (a >= 0.0f) ? a : 0.01f * a;
        b = (b >= 0.0f) ? b : 0.01f * b;
        __nv_bfloat16 ha = __float2bfloat16(a);
        __nv_bfloat16 hb = __float2bfloat16(b);
        float la = a - __bfloat162float(ha);
        float lb = b - __bfloat162float(hb);
        __nv_bfloat162 hv; hv.x = ha; hv.y = hb;
        hw[p] = *(uint32_t*)&hv;
        lw[p] = pack_bf2(la, lb);
    }
    *(uint4*)(out + (size_t)i * 2048 + j0)        = hp;
    *(uint4*)(out + (size_t)i * 2048 + 1024 + j0) = lp;
}

// ---------------------------------------------------------------------------
// HMMA GEMM: C[B,N] = act(A @ W^T + bias), split-bf16 3-pass accumulate.
//   CTA tile 128x128, 8 warps (2x4), warp tile 64x32, mma m16n8k16.
//   BK=64 (128B rows, XOR swizzle), cp.async 3-stage pipeline, 48 chunks.
// ---------------------------------------------------------------------------
#define NCHUNK 48
#define SMEM_REQ 98816   // 3*32KB slots + align pad

template<int ACT, int OUT_SPLIT>
__global__ void __launch_bounds__(256, 2)
mma_gemm(const __nv_bfloat16* __restrict__ A2,
         const __nv_bfloat16* __restrict__ BT,
         const float* __restrict__ bias,
         void* __restrict__ outp)
{
    extern __shared__ char dsmem[];
    const uint32_t sraw = smem_u32(dsmem);
    const uint32_t S = (sraw + 127u) & ~127u;
    char* Sp = dsmem + (S - sraw);

    const int tid = threadIdx.x;
    const int lane = tid & 31;
    const int wid = tid >> 5;
    const int warp_m = wid & 1;     // 2 warp-rows of 64
    const int warp_n = wid >> 1;    // 4 warp-cols of 32
    const int rowBase = blockIdx.y * 128;
    const int colBase = blockIdx.x * 128;

    const int ldRow = tid >> 3;   // 0..31 (+32/iter)
    const int ldCh  = tid & 7;    // 16B chunk within 128B row

    float acc[4][4][4];
    #pragma unroll
    for (int i = 0; i < 4; i++)
        #pragma unroll
        for (int j = 0; j < 4; j++)
            #pragma unroll
            for (int r = 0; r < 4; r++) acc[i][j][r] = 0.0f;

    // slot s: A tile at S + s*32768, B tile at S + s*32768 + 16384
    auto load_chunk = [&](int c, int slot) {
        const int pass = c >> 4, kc = c & 15;
        const int aCol = ((pass == 1) ? 1024 : 0) + kc * 64;
        const int bCol = ((pass == 2) ? 1024 : 0) + kc * 64;
        const uint32_t aT = S + slot * 32768;
        const uint32_t bT = aT + 16384;
        #pragma unroll
        for (int it = 0; it < 4; it++) {
            int row = ldRow + it * 32;
            const void* src = A2 + (size_t)(rowBase + row) * 2048 + aCol + ldCh * 8;
            uint32_t dst = aT + row * 128 + ((ldCh ^ (row & 7)) * 16);
            asm volatile("cp.async.cg.shared.global [%0], [%1], 16;\n"
                         :: "r"(dst), "l"(src));
        }
        #pragma unroll
        for (int it = 0; it < 4; it++) {
            int row = ldRow + it * 32;
            const void* src = BT + (size_t)(colBase + row) * 2048 + bCol + ldCh * 8;
            uint32_t dst = bT + row * 128 + ((ldCh ^ (row & 7)) * 16);
            asm volatile("cp.async.cg.shared.global [%0], [%1], 16;\n"
                         :: "r"(dst), "l"(src));
        }
        asm volatile("cp.async.commit_group;\n");
    };

    load_chunk(0, 0);
    load_chunk(1, 1);

    // ldmatrix lane mapping
    const int aR = lane & 15;        // row within 16-row m-tile
    const int aH = lane >> 4;        // k half (16B chunk +0/+1)
    const int bR = lane & 7;
    const int bQ = lane >> 3;        // quad 0..3

    for (int c = 0; c < NCHUNK; c++) {
        const int slot = c % 3;
        if (c + 1 < NCHUNK)
            asm volatile("cp.async.wait_group 1;\n" ::: "memory");
        else
            asm volatile("cp.async.wait_group 0;\n" ::: "memory");
        __syncthreads();   // chunk c visible; all warps done with slot (c+2)%3's old data

        if (c + 2 < NCHUNK)
            load_chunk(c + 2, (c + 2) % 3);

        const uint32_t aT = S + slot * 32768;
        const uint32_t bT = aT + 16384;

        #pragma unroll
        for (int ks = 0; ks < 4; ks++) {
            uint32_t bfr[4][2];
            #pragma unroll
            for (int p = 0; p < 2; p++) {
                int nrow = warp_n * 32 + p * 16 + (bQ >> 1) * 8 + bR;
                int ch = ks * 2 + (bQ & 1);
                uint32_t addr = bT + nrow * 128 + ((ch ^ (nrow & 7)) * 16);
                uint32_t x0, x1, x2, x3;
                asm volatile("ldmatrix.sync.aligned.m8n8.x4.shared.b16 "
                             "{%0,%1,%2,%3}, [%4];"
                             : "=r"(x0), "=r"(x1), "=r"(x2), "=r"(x3) : "r"(addr));
                bfr[p * 2 + 0][0] = x0; bfr[p * 2 + 0][1] = x1;
                bfr[p * 2 + 1][0] = x2; bfr[p * 2 + 1][1] = x3;
            }
            #pragma unroll
            for (int i = 0; i < 4; i++) {
                int arow = warp_m * 64 + i * 16 + aR;
                int ch = ks * 2 + aH;
                uint32_t addr = aT + arow * 128 + ((ch ^ (arow & 7)) * 16);
                uint32_t a0, a1, a2, a3;
                asm volatile("ldmatrix.sync.aligned.m8n8.x4.shared.b16 "
                             "{%0,%1,%2,%3}, [%4];"
                             : "=r"(a0), "=r"(a1), "=r"(a2), "=r"(a3) : "r"(addr));
                #pragma unroll
                for (int j = 0; j < 4; j++) {
                    asm volatile(
                        "mma.sync.aligned.m16n8k16.row.col.f32.bf16.bf16.f32 "
                        "{%0,%1,%2,%3}, {%4,%5,%6,%7}, {%8,%9}, {%0,%1,%2,%3};"
                        : "+f"(acc[i][j][0]), "+f"(acc[i][j][1]),
                          "+f"(acc[i][j][2]), "+f"(acc[i][j][3])
                        : "r"(a0), "r"(a1), "r"(a2), "r"(a3),
                          "r"(bfr[j][0]), "r"(bfr[j][1]));
                }
            }
        }
    }
    __syncthreads();   // all warps done reading smem before epilogue reuse

    // ---------------- epilogue: stage fp32 -> smem, then coalesced out ------
    float* stg = (float*)Sp;          // [128][132] = 67.6KB < 96KB
    const int g = lane >> 2, t = lane & 3;
    #pragma unroll
    for (int i = 0; i < 4; i++) {
        int r0 = warp_m * 64 + i * 16 + g;
        #pragma unroll
        for (int j = 0; j < 4; j++) {
            int cc = warp_n * 32 + j * 8 + t * 2;
            *(float2*)&stg[r0 * 132 + cc]       = make_float2(acc[i][j][0], acc[i][j][1]);
            *(float2*)&stg[(r0 + 8) * 132 + cc] = make_float2(acc[i][j][2], acc[i][j][3]);
        }
    }
    __syncthreads();

    if (OUT_SPLIT) {
        __nv_bfloat16* O = (__nv_bfloat16*)outp;
        for (int idx = tid; idx < 128 * 64; idx += 256) {
            int row = idx >> 6, cc = (idx & 63) * 2;
            float v0 = stg[row * 132 + cc]     + bias[colBase + cc];
            float v1 = stg[row * 132 + cc + 1] + bias[colBase + cc + 1];
            if (ACT == 0) {
                v0 = (v0 >= 0.0f) ? v0 : 0.01f * v0;
                v1 = (v1 >= 0.0f) ? v1 : 0.01f * v1;
            } else {
                v0 = tanhf(v0); v1 = tanhf(v1);
            }
            __nv_bfloat16 h0 = __float2bfloat16(v0);
            __nv_bfloat16 h1 = __float2bfloat16(v1);
            float l0 = v0 - __bfloat162float(h0);
            float l1 = v1 - __bfloat162float(h1);
            size_t base = (size_t)(rowBase + row) * 2048 + colBase + cc;
            __nv_bfloat162 hv; hv.x = h0; hv.y = h1;
            *(uint32_t*)(O + base)        = *(uint32_t*)&hv;
            *(uint32_t*)(O + base + 1024) = pack_bf2(l0, l1);
        }
    } else {
        float* O = (float*)outp;
        for (int idx = tid; idx < 128 * 128; idx += 256) {
            int row = idx >> 7, cc = idx & 127;
            float v = stg[row * 132 + cc] + bias[colBase + cc];
            if (ACT == 0) v = (v >= 0.0f) ? v : 0.01f * v;
            else          v = tanhf(v);
            O[(size_t)(rowBase + row) * 256 + colBase + cc] = v;
        }
    }
}

// ---------------------------------------------------------------------------
// FK chain: one thread per row. Bottom homogeneous row stays (0,0,0,1),
// fp32(1 + 1e-9) == 1, so the final divide is identity.
// ---------------------------------------------------------------------------
__global__ void fk_kernel(const float* __restrict__ joints,
                          float* __restrict__ out)
{
    int row = blockIdx.x * blockDim.x + threadIdx.x;
    if (row >= B_ROWS) return;

    const float* q = joints + (size_t)row * NJOUT;
    float* o = out + (size_t)row * (NJ * 3);

    float M00 = 1, M01 = 0, M02 = 0;
    float M10 = 0, M11 = 1, M12 = 0;
    float M20 = 0, M21 = 0, M22 = 1;
    float px = 0, py = 0, pz = 0;

    for (int j = 0; j < NJ; j++) {
        float4 qv = *(const float4*)(q + 4 * j);
        float w = qv.x, x = qv.y, y = qv.z, z = qv.w;
        float s = 2.0f / (w * w + x * x + y * y + z * z);

        float r00 = 1.0f - s * (y * y + z * z);
        float r01 = s * (x * y - z * w);
        float r02 = s * (x * z + y * w);
        float r10 = s * (x * y + z * w);
        float r11 = 1.0f - s * (x * x + z * z);
        float r12 = s * (y * z - x * w);
        float r20 = s * (x * z - y * w);
        float r21 = s * (y * z + x * w);
        float r22 = 1.0f - s * (x * x + y * y);

        float tx = M00 * r01 + M01 * r11 + M02 * r21 + px;
        float ty = M10 * r01 + M11 * r11 + M12 * r21 + py;
        float tz = M20 * r01 + M21 * r11 + M22 * r21 + pz;

        float n00 = M00 * r00 + M01 * r10 + M02 * r20;
        float n01 = M00 * r01 + M01 * r11 + M02 * r21;
        float n02 = M00 * r02 + M01 * r12 + M02 * r22;
        float n10 = M10 * r00 + M11 * r10 + M12 * r20;
        float n11 = M10 * r01 + M11 * r11 + M12 * r21;
        float n12 = M10 * r02 + M11 * r12 + M12 * r22;
        float n20 = M20 * r00 + M21 * r10 + M22 * r20;
        float n21 = M20 * r01 + M21 * r11 + M22 * r21;
        float n22 = M20 * r02 + M21 * r12 + M22 * r22;

        M00 = n00; M01 = n01; M02 = n02;
        M10 = n10; M11 = n11; M12 = n12;
        M20 = n20; M21 = n21; M22 = n22;
        px = tx; py = ty; pz = tz;

        o[3 * j + 0] = px;
        o[3 * j + 1] = py;
        o[3 * j + 2] = pz;
    }
}

// ---------------------------------------------------------------------------
extern "C" void kernel_launch(void* const* d_in, const int* in_sizes, int n_in,
                              void* d_out, int out_size)
{
    const float* x  = (const float*)d_in[0];
    const float* W1 = (const float*)d_in[1];
    const float* b1 = (const float*)d_in[2];
    const float* W2 = (const float*)d_in[3];
    const float* b2 = (const float*)d_in[4];
    const float* W3 = (const float*)d_in[5];
    const float* b3 = (const float*)d_in[6];
    const float* W4 = (const float*)d_in[7];
    const float* b4 = (const float*)d_in[8];
    float* out = (float*)d_out;

    void *p_a0, *p_a1, *p_w2, *p_w3, *p_w4, *p_jt;
    cudaGetSymbolAddress(&p_a0, g_act0);
    cudaGetSymbolAddress(&p_a1, g_act1);
    cudaGetSymbolAddress(&p_w2, g_w2t);
    cudaGetSymbolAddress(&p_w3, g_w3t);
    cudaGetSymbolAddress(&p_w4, g_w4t);
    cudaGetSymbolAddress(&p_jt, g_joints);
    __nv_bfloat16* a0  = (__nv_bfloat16*)p_a0;
    __nv_bfloat16* a1  = (__nv_bfloat16*)p_a1;
    __nv_bfloat16* w2t = (__nv_bfloat16*)p_w2;
    __nv_bfloat16* w3t = (__nv_bfloat16*)p_w3;
    __nv_bfloat16* w4t = (__nv_bfloat16*)p_w4;
    float* jt = (float*)p_jt;

    cudaFuncSetAttribute(mma_gemm<0, 1>, cudaFuncAttributeMaxDynamicSharedMemorySize, SMEM_REQ);
    cudaFuncSetAttribute(mma_gemm<1, 0>, cudaFuncAttributeMaxDynamicSharedMemorySize, SMEM_REQ);

    // Weight split+transpose (tiled, coalesced)
    {
        dim3 blk(32, 8);
        wsplit_kernel<<<dim3(HID / 32, HID / 32), blk>>>(W2, w2t, HID, HID);
        wsplit_kernel<<<dim3(HID / 32, HID / 32), blk>>>(W3, w3t, HID, HID);
        wsplit_kernel<<<dim3(NJOUT / 32, HID / 32), blk>>>(W4, w4t, HID, NJOUT);
    }

    // Layer 1 (fp32, K=3) -> split act, 8 outputs per thread
    layer1_kernel<<<(B_ROWS * 128) / 256, 256>>>(x, W1, b1, a0);

    // Layers 2-4 on HMMA tensor cores
    {
        dim3 grid(HID / 128, B_ROWS / 128);
        mma_gemm<0, 1><<<grid, 256, SMEM_REQ>>>(a0, w2t, b2, a1);
        mma_gemm<0, 1><<<grid, 256, SMEM_REQ>>>(a1, w3t, b3, a0);
    }
    {
        dim3 grid(NJOUT / 128, B_ROWS / 128);
        mma_gemm<1, 0><<<grid, 256, SMEM_REQ>>>(a0, w4t, b4, jt);
    }

    // FK chain
    fk_kernel<<<B_ROWS / 128, 128>>>(jt, out);
}